// round 4
// baseline (speedup 1.0000x reference)
#include <cuda_runtime.h>
#include <cstdint>

// LIF neuron scan — fully bulk-async: UBLKCP G->S input pipeline,
// UBLKCP S->G bulk-group output stores. Warps only do LDS + FMA chain + STS.
//
// Inputs : d_in[0] = input_current  f32 [B=32, T=1000, N=1024]
//          d_in[1] = v_init         f32 [B=32, N=1024]
// Output : d_out = [2, B, T, N] f32  (spikes block, then voltages block)
//
// Recurrence:
//   v = v + (i - v) / 10.0     (correctly-rounded div via Markstein FMA seq)
//   s = (v >= 1.0) ? 1 : 0
//   v = s ? 0 : v

#define LIF_B   32
#define LIF_T   1000
#define LIF_N   1024
#define TC      20                 // timesteps per chunk
#define NSTAGE  4                  // input pipeline depth
#define NPC     128                // neurons per CTA
#define NTHREAD 64                 // threads per CTA (2 neurons each, float2)
#define NCHUNK  (LIF_T / TC)       // 50
#define ROW_BYTES (NPC * 4)        // 512
#define STAGE_BYTES (TC * ROW_BYTES)  // 10240

struct LifSmem {
    float in_tile[NSTAGE][TC][NPC];   // 40960 B
    float out_sp[2][TC][NPC];         // 10240 B x2
    float out_vp[2][TC][NPC];         // 10240 B x2
    unsigned long long mbar[NSTAGE];
};

static __device__ __forceinline__ unsigned smem_u32(const void* p) {
    return (unsigned)__cvta_generic_to_shared(p);
}

static __device__ __forceinline__ void mbar_init(unsigned mbar, unsigned count) {
    asm volatile("mbarrier.init.shared.b64 [%0], %1;" :: "r"(mbar), "r"(count) : "memory");
}

static __device__ __forceinline__ void mbar_expect_tx(unsigned mbar, unsigned bytes) {
    asm volatile("mbarrier.arrive.expect_tx.shared.b64 _, [%0], %1;"
                 :: "r"(mbar), "r"(bytes) : "memory");
}

static __device__ __forceinline__ void mbar_wait(unsigned mbar, unsigned parity) {
    asm volatile(
        "{\n\t"
        ".reg .pred P1;\n\t"
        "LAB_WAIT_%=:\n\t"
        "mbarrier.try_wait.parity.acquire.cta.shared::cta.b64 P1, [%0], %1, 0x989680;\n\t"
        "@P1 bra LAB_DONE_%=;\n\t"
        "bra LAB_WAIT_%=;\n\t"
        "LAB_DONE_%=:\n\t"
        "}"
        :: "r"(mbar), "r"(parity) : "memory");
}

static __device__ __forceinline__ void bulk_g2s(unsigned dst_smem, const void* gsrc,
                                                unsigned bytes, unsigned mbar) {
    asm volatile(
        "cp.async.bulk.shared::cta.global.mbarrier::complete_tx::bytes [%0], [%1], %2, [%3];"
        :: "r"(dst_smem), "l"(gsrc), "r"(bytes), "r"(mbar) : "memory");
}

static __device__ __forceinline__ void bulk_s2g(void* gdst, unsigned src_smem,
                                                unsigned bytes) {
    asm volatile(
        "cp.async.bulk.global.shared::cta.bulk_group [%0], [%1], %2;"
        :: "l"(gdst), "r"(src_smem), "r"(bytes) : "memory");
}

static __device__ __forceinline__ void bulk_commit() {
    asm volatile("cp.async.bulk.commit_group;" ::: "memory");
}

static __device__ __forceinline__ void bulk_wait_read_1() {
    asm volatile("cp.async.bulk.wait_group.read 1;" ::: "memory");
}

static __device__ __forceinline__ void bulk_wait_0() {
    asm volatile("cp.async.bulk.wait_group 0;" ::: "memory");
}

static __device__ __forceinline__ float lif_step(float v, float i, float& s_out) {
    float x  = i - v;                  // (-(v - 0) + i)
    float q0 = x * 0.1f;               // Markstein: correctly-rounded x/10
    float e  = fmaf(-10.0f, q0, x);
    float q  = fmaf(e, 0.1f, q0);
    v = v + q;
    s_out = (v >= 1.0f) ? 1.0f : 0.0f;
    return (v >= 1.0f) ? 0.0f : v;
}

static __device__ __forceinline__ void issue_in_chunk(LifSmem* sm, int c, const float* gsrc) {
    const int s = c & (NSTAGE - 1);
    const unsigned mb = smem_u32(&sm->mbar[s]);
    mbar_expect_tx(mb, STAGE_BYTES);
    #pragma unroll
    for (int r = 0; r < TC; ++r) {
        const float* src = gsrc + (long long)(c * TC + r) * LIF_N;
        bulk_g2s(smem_u32(&sm->in_tile[s][r][0]), src, ROW_BYTES, mb);
    }
}

static __global__ __launch_bounds__(NTHREAD)
void lif_scan_kernel(const float* __restrict__ in,
                     const float* __restrict__ v0,
                     float* __restrict__ out)
{
    extern __shared__ char smem_raw[];
    LifSmem* sm = reinterpret_cast<LifSmem*>(smem_raw);

    const int tid = threadIdx.x;
    const int b   = blockIdx.x >> 3;          // 32 batches
    const int n0  = (blockIdx.x & 7) * NPC;   // 8 neuron-blocks of 128

    if (tid == 0) {
        #pragma unroll
        for (int i = 0; i < NSTAGE; ++i)
            mbar_init(smem_u32(&sm->mbar[i]), 1);
        asm volatile("fence.proxy.async.shared::cta;" ::: "memory");
    }
    __syncthreads();

    const float* gsrc = in + (long long)b * (LIF_T * LIF_N) + n0;
    float* gsp = out + (long long)b * (LIF_T * LIF_N) + n0;            // spikes
    float* gvp = gsp + (long long)LIF_B * LIF_T * LIF_N;               // voltages

    // Prologue: fill the input pipeline.
    if (tid == 0) {
        #pragma unroll
        for (int c = 0; c < NSTAGE; ++c)
            issue_in_chunk(sm, c, gsrc);
    }

    // Per-thread state: 2 neurons.
    float2 v = *(const float2*)(v0 + (long long)b * LIF_N + n0 + 2 * tid);

    #pragma unroll 1
    for (int c = 0; c < NCHUNK; ++c) {
        const int s  = c & (NSTAGE - 1);
        const int os = c & 1;
        const unsigned parity = (c >> 2) & 1;

        // Input stage s filled?
        mbar_wait(smem_u32(&sm->mbar[s]), parity);

        // Output stage os reusable? (keep <=1 committed group in flight)
        if (tid == 32) bulk_wait_read_1();
        __syncthreads();

        #pragma unroll
        for (int r = 0; r < TC; ++r) {
            float2 cur = ((const float2*)&sm->in_tile[s][r][0])[tid];
            float s0, s1;
            v.x = lif_step(v.x, cur.x, s0);
            v.y = lif_step(v.y, cur.y, s1);
            ((float2*)&sm->out_sp[os][r][0])[tid] = make_float2(s0, s1);
            ((float2*)&sm->out_vp[os][r][0])[tid] = v;
        }

        // Make STS visible to the async proxy, then let electees issue.
        asm volatile("fence.proxy.async.shared::cta;" ::: "memory");
        __syncthreads();

        if (tid == 0 && c + NSTAGE < NCHUNK)
            issue_in_chunk(sm, c + NSTAGE, gsrc);

        if (tid == 32) {
            #pragma unroll
            for (int r = 0; r < TC; ++r) {
                const long long off = (long long)(c * TC + r) * LIF_N;
                bulk_s2g(gsp + off, smem_u32(&sm->out_sp[os][r][0]), ROW_BYTES);
                bulk_s2g(gvp + off, smem_u32(&sm->out_vp[os][r][0]), ROW_BYTES);
            }
            bulk_commit();
        }
    }

    // Flush all pending bulk stores before exit.
    if (tid == 32) bulk_wait_0();
}

extern "C" void kernel_launch(void* const* d_in, const int* in_sizes, int n_in,
                              void* d_out, int out_size)
{
    const float* in = (const float*)d_in[0];   // [B, T, N]
    const float* v0 = (const float*)d_in[1];   // [B, N]
    float* out = (float*)d_out;                // [2, B, T, N]

    (void)in_sizes; (void)n_in; (void)out_size;

    const int smem_bytes = (int)sizeof(LifSmem);   // ~82 KB
    cudaFuncSetAttribute(lif_scan_kernel,
                         cudaFuncAttributeMaxDynamicSharedMemorySize, smem_bytes);

    const int grid = LIF_B * (LIF_N / NPC);    // 256 CTAs
    lif_scan_kernel<<<grid, NTHREAD, smem_bytes>>>(in, v0, out);
}

// round 5
// speedup vs baseline: 1.1541x; 1.1541x over previous
#include <cuda_runtime.h>
#include <cstdint>

// LIF neuron scan — R3 skeleton (TMA reads -> SMEM, register compute, __stcs
// writes) with balanced grid (128 CTAs, 1/SM), 4 warps/CTA, lane-parallel TMA
// issue, and a 5-deep 100 KB input pipeline.
//
// Inputs : d_in[0] = input_current  f32 [B=32, T=1000, N=1024]
//          d_in[1] = v_init         f32 [B=32, N=1024]
// Output : d_out = [2, B, T, N] f32  (spikes block, then voltages block)
//
// Recurrence:
//   v = v + (i - v) / 10.0     (correctly-rounded div via Markstein FMA seq)
//   s = (v >= 1.0) ? 1 : 0
//   v = s ? 0 : v

#define LIF_B   32
#define LIF_T   1000
#define LIF_N   1024
#define TC      20                    // timesteps per chunk
#define NSTAGE  5                     // input pipeline depth
#define NPC     256                   // neurons per CTA
#define NTHREAD 128                   // threads per CTA (2 neurons each)
#define NCHUNK  (LIF_T / TC)          // 50
#define ROW_BYTES (NPC * 4)           // 1024
#define STAGE_BYTES (TC * ROW_BYTES)  // 20480

struct LifSmem {
    float tile[NSTAGE][TC][NPC];      // 102400 B
    unsigned long long mbar[NSTAGE];
};

static __device__ __forceinline__ unsigned smem_u32(const void* p) {
    return (unsigned)__cvta_generic_to_shared(p);
}

static __device__ __forceinline__ void mbar_init(unsigned mbar, unsigned count) {
    asm volatile("mbarrier.init.shared.b64 [%0], %1;" :: "r"(mbar), "r"(count) : "memory");
}

static __device__ __forceinline__ void mbar_expect_tx(unsigned mbar, unsigned bytes) {
    asm volatile("mbarrier.arrive.expect_tx.shared.b64 _, [%0], %1;"
                 :: "r"(mbar), "r"(bytes) : "memory");
}

static __device__ __forceinline__ void mbar_wait(unsigned mbar, unsigned parity) {
    asm volatile(
        "{\n\t"
        ".reg .pred P1;\n\t"
        "LAB_WAIT_%=:\n\t"
        "mbarrier.try_wait.parity.acquire.cta.shared::cta.b64 P1, [%0], %1, 0x989680;\n\t"
        "@P1 bra LAB_DONE_%=;\n\t"
        "bra LAB_WAIT_%=;\n\t"
        "LAB_DONE_%=:\n\t"
        "}"
        :: "r"(mbar), "r"(parity) : "memory");
}

static __device__ __forceinline__ void bulk_g2s(unsigned dst_smem, const void* gsrc,
                                                unsigned bytes, unsigned mbar) {
    asm volatile(
        "cp.async.bulk.shared::cta.global.mbarrier::complete_tx::bytes [%0], [%1], %2, [%3];"
        :: "r"(dst_smem), "l"(gsrc), "r"(bytes), "r"(mbar) : "memory");
}

static __device__ __forceinline__ float lif_step(float v, float i, float& s_out) {
    float x  = i - v;                  // (-(v - 0) + i)
    float q0 = x * 0.1f;               // Markstein: correctly-rounded x/10
    float e  = fmaf(-10.0f, q0, x);
    float q  = fmaf(e, 0.1f, q0);
    v = v + q;
    s_out = (v >= 1.0f) ? 1.0f : 0.0f;
    return (v >= 1.0f) ? 0.0f : v;
}

// Warp 0 only. Lane 0 posts expect_tx; lanes 0..TC-1 each issue one row copy.
// Warp-level program order guarantees expect_tx issues before the copies.
static __device__ __forceinline__ void issue_chunk_warp0(LifSmem* sm, int c,
                                                         const float* gsrc, int lane) {
    const int s = c % NSTAGE;
    const unsigned mb = smem_u32(&sm->mbar[s]);
    if (lane == 0) mbar_expect_tx(mb, STAGE_BYTES);
    if (lane < TC) {
        const float* src = gsrc + (long long)(c * TC + lane) * LIF_N;
        bulk_g2s(smem_u32(&sm->tile[s][lane][0]), src, ROW_BYTES, mb);
    }
}

static __global__ __launch_bounds__(NTHREAD)
void lif_scan_kernel(const float* __restrict__ in,
                     const float* __restrict__ v0,
                     float* __restrict__ out)
{
    extern __shared__ char smem_raw[];
    LifSmem* sm = reinterpret_cast<LifSmem*>(smem_raw);

    const int tid  = threadIdx.x;
    const int lane = tid & 31;
    const int b    = blockIdx.x >> 2;          // 32 batches
    const int n0   = (blockIdx.x & 3) * NPC;   // 4 neuron-blocks of 256

    if (tid == 0) {
        #pragma unroll
        for (int i = 0; i < NSTAGE; ++i)
            mbar_init(smem_u32(&sm->mbar[i]), 1);
        asm volatile("fence.proxy.async.shared::cta;" ::: "memory");
    }
    __syncthreads();

    const float* gsrc = in + (long long)b * (LIF_T * LIF_N) + n0;

    // Prologue: fill all pipeline stages (warp 0, lane-parallel issue).
    if (tid < 32) {
        #pragma unroll
        for (int c = 0; c < NSTAGE; ++c)
            issue_chunk_warp0(sm, c, gsrc, lane);
    }

    // Per-thread state: 2 neurons.
    float2 v = *(const float2*)(v0 + (long long)b * LIF_N + n0 + 2 * tid);

    float* sp = out + (long long)b * (LIF_T * LIF_N) + n0 + 2 * tid;   // spikes
    float* vp = sp + (long long)LIF_B * LIF_T * LIF_N;                 // voltages

    #pragma unroll 1
    for (int c = 0; c < NCHUNK; ++c) {
        const int s = c % NSTAGE;
        const unsigned parity = (c / NSTAGE) & 1;

        mbar_wait(smem_u32(&sm->mbar[s]), parity);

        #pragma unroll
        for (int r = 0; r < TC; ++r) {
            float2 cur = ((const float2*)&sm->tile[s][r][0])[tid];
            float s0, s1;
            v.x = lif_step(v.x, cur.x, s0);
            v.y = lif_step(v.y, cur.y, s1);
            const long long off = (long long)(c * TC + r) * LIF_N;
            __stcs((float2*)(sp + off), make_float2(s0, s1));
            __stcs((float2*)(vp + off), v);
        }

        __syncthreads();   // all threads done reading stage s -> safe to refill

        if (tid < 32 && c + NSTAGE < NCHUNK)
            issue_chunk_warp0(sm, c + NSTAGE, gsrc, lane);
    }
}

extern "C" void kernel_launch(void* const* d_in, const int* in_sizes, int n_in,
                              void* d_out, int out_size)
{
    const float* in = (const float*)d_in[0];   // [B, T, N]
    const float* v0 = (const float*)d_in[1];   // [B, N]
    float* out = (float*)d_out;                // [2, B, T, N]

    (void)in_sizes; (void)n_in; (void)out_size;

    const int smem_bytes = (int)sizeof(LifSmem);   // ~100 KB
    cudaFuncSetAttribute(lif_scan_kernel,
                         cudaFuncAttributeMaxDynamicSharedMemorySize, smem_bytes);

    const int grid = LIF_B * (LIF_N / NPC);    // 128 CTAs -> <=1 per SM
    lif_scan_kernel<<<grid, NTHREAD, smem_bytes>>>(in, v0, out);
}